// round 3
// baseline (speedup 1.0000x reference)
#include <cuda_runtime.h>
#include <cuda_bf16.h>

// AttentionRouting: u [B=4, I=32, N=32, J=16, H=32, W=32] f32, bias [1,32,32,1,1,1]
//   v = sum_i u; c_raw = sum_j u*v; c = softmax_n(0.25*c_raw) + bias
//   s = sum_i u*c; squash over j.
//
// Per-b phasing: K1(b) -> K2(b) -> K3(b). K3 re-reads u[b] (64MB) from L2,
// since K1(b) just streamed it. K1 tiles w in halves (32KB smem) for 75% occ.

#define BB 4
#define II 32
#define NN 32
#define JJ 16
#define HH 32
#define WW 32
#define HW 1024
#define STRIDE_I 524288   // N*J*H*W
#define WT 16             // w tile

// per-b scratch (reused across b): c_raw [I,N,H,W] 4MB, lse [I,H,W] 128KB
__device__ float g_craw[II * NN * HW];
__device__ float g_lse[II * HW];

// ---------------------------------------------------------------------------
// K1: per (n, h, w-half) slice of batch b. 256 threads, 32KB+5KB smem.
// Computes v during load (register partials), then c_raw, writes c_raw.
// ---------------------------------------------------------------------------
__global__ void __launch_bounds__(256) k1_craw(const float* __restrict__ u,
                                               int b) {
    __shared__ float u_s[II * JJ * WT];            // 32 KB
    __shared__ float4 vpart[256];                  // 4 KB
    __shared__ float v_s[JJ * WT];                 // 1 KB

    const int bid = blockIdx.x;                    // (n*HH + h)*2 + wh
    const int wh = bid & 1;
    const int h = (bid >> 1) & 31;
    const int n = bid >> 6;
    const int w0 = wh * WT;
    const int tid = threadIdx.x;

    // u element: ((b*II+i)*NN+n)*JJ*HW + j*HW + h*WW + w
    const int base = (b * 1024 + n) * (JJ * HW) + h * WW + w0;

    // load: q = float4 within w-tile (4), j (16), iq = i mod 4 group (4)
    const int q = tid & 3;
    const int j = (tid >> 2) & 15;
    const int iq = tid >> 6;

    float4 vp = make_float4(0.f, 0.f, 0.f, 0.f);
#pragma unroll
    for (int k = 0; k < 8; k++) {
        const int i = 4 * k + iq;
        const float4 val =
            *(const float4*)(u + base + i * STRIDE_I + j * HW + q * 4);
        *(float4*)(&u_s[(i * JJ + j) * WT + q * 4]) = val;
        vp.x += val.x; vp.y += val.y; vp.z += val.z; vp.w += val.w;
    }
    vpart[tid] = vp;
    __syncthreads();

    // combine 4 iq-groups -> v[j][w]
    if (tid < 64) {                                // tid<64 keeps same (j,q)
        const float4 a = vpart[tid];
        const float4 c2 = vpart[tid + 64];
        const float4 c3 = vpart[tid + 128];
        const float4 c4 = vpart[tid + 192];
        float4 r;
        r.x = a.x + c2.x + c3.x + c4.x;
        r.y = a.y + c2.y + c3.y + c4.y;
        r.z = a.z + c2.z + c3.z + c4.z;
        r.w = a.w + c2.w + c3.w + c4.w;
        *(float4*)(&v_s[j * WT + q * 4]) = r;
    }
    __syncthreads();

    // c_raw[i][w] = sum_j u_s[i][j][w] * v[j][w]
    const int wl = tid & 15;
    const int i0 = tid >> 4;                       // 0..15
    float vreg[JJ];
#pragma unroll
    for (int jj = 0; jj < JJ; jj++) vreg[jj] = v_s[jj * WT + wl];

#pragma unroll
    for (int m = 0; m < 2; m++) {
        const int i = i0 + 16 * m;
        float acc = 0.f;
#pragma unroll
        for (int jj = 0; jj < JJ; jj++)
            acc += u_s[(i * JJ + jj) * WT + wl] * vreg[jj];
        g_craw[(i * NN + n) * HW + h * WW + w0 + wl] = acc;
    }
}

// ---------------------------------------------------------------------------
// K2: per-pixel (i,h,w) log-sum-exp over n of 0.25*c_raw (batch b implicit).
// ---------------------------------------------------------------------------
__global__ void __launch_bounds__(256) k2_lse() {
    const int t = blockIdx.x * 256 + threadIdx.x;  // 0..32767
    const int hw = t & 1023;
    const int i = t >> 10;
    const float* p = g_craw + i * (NN * HW) + hw;

    float vals[NN];
    float m = -3.402823466e+38f;
#pragma unroll
    for (int n = 0; n < NN; n++) {
        vals[n] = 0.25f * p[n * HW];
        m = fmaxf(m, vals[n]);
    }
    float s = 0.f;
#pragma unroll
    for (int n = 0; n < NN; n++) s += expf(vals[n] - m);
    g_lse[t] = m + logf(s);
}

// ---------------------------------------------------------------------------
// K3: per (n, h) slice of batch b, 512 threads (j,w). u reads hit L2.
// c[i,w] = exp(0.25*c_raw - lse) + bias[i,n]; s[j,w] = sum_i u*c; squash.
// ---------------------------------------------------------------------------
__global__ void __launch_bounds__(512) k3_out(const float* __restrict__ u,
                                             const float* __restrict__ bias,
                                             float* __restrict__ out, int b) {
    __shared__ float c_s[II * WW];                 // 4 KB
    __shared__ float s_s[JJ * WW];                 // 2 KB

    const int bid = blockIdx.x;                    // n*HH + h
    const int h = bid & 31;
    const int n = bid >> 5;
    const int tid = threadIdx.x;

#pragma unroll
    for (int t = tid; t < II * WW; t += 512) {
        const int i = t >> 5;
        const int w = t & 31;
        const int hw = h * WW + w;
        const float cr = g_craw[(i * NN + n) * HW + hw];
        const float lse = g_lse[i * HW + hw];
        c_s[t] = expf(0.25f * cr - lse) + __ldg(&bias[i * NN + n]);
    }
    __syncthreads();

    const int jj = tid >> 5;                       // 0..15
    const int w = tid & 31;
    const int base = (b * 1024 + n) * (JJ * HW) + h * WW + w + jj * HW;

    float a0 = 0.f, a1 = 0.f, a2 = 0.f, a3 = 0.f;
#pragma unroll
    for (int i = 0; i < II; i += 4) {
        a0 += u[base + (i + 0) * STRIDE_I] * c_s[(i + 0) * 32 + w];
        a1 += u[base + (i + 1) * STRIDE_I] * c_s[(i + 1) * 32 + w];
        a2 += u[base + (i + 2) * STRIDE_I] * c_s[(i + 2) * 32 + w];
        a3 += u[base + (i + 3) * STRIDE_I] * c_s[(i + 3) * 32 + w];
    }
    const float acc = (a0 + a1) + (a2 + a3);

    s_s[tid] = acc;
    __syncthreads();

    float nrm2 = 0.f;
#pragma unroll
    for (int j2 = 0; j2 < JJ; j2++) {
        const float x = s_s[j2 * WW + w];
        nrm2 += x * x;
    }
    const float nrm = sqrtf(nrm2);
    const float factor =
        (1.0f - 1.0f / (expf(nrm) + 1e-20f)) / (nrm + 1e-20f);

    out[((b * NN + n) * JJ + jj) * HW + h * WW + w] = acc * factor;
}

// ---------------------------------------------------------------------------
extern "C" void kernel_launch(void* const* d_in, const int* in_sizes, int n_in,
                              void* d_out, int out_size) {
    const float* u = (const float*)d_in[0];
    const float* bias = (const float*)d_in[1];
    float* out = (float*)d_out;

    for (int b = 0; b < BB; b++) {
        k1_craw<<<NN * HH * 2, 256>>>(u, b);       // 2048 CTAs
        k2_lse<<<(II * HW) / 256, 256>>>();        // 128 CTAs
        k3_out<<<NN * HH, 512>>>(u, bias, out, b); // 1024 CTAs
    }
}

// round 4
// speedup vs baseline: 1.1408x; 1.1408x over previous
#include <cuda_runtime.h>
#include <cuda_bf16.h>

// AttentionRouting: u [B=4, I=32, N=32, J=16, H=32, W=32] f32, bias [1,32,32,1,1,1]
//   v = sum_i u; c_raw = sum_j u*v; c = softmax_n(0.25*c_raw) + bias
//   s = sum_i u*c; squash over j.
//
// R4 plan: K1 single launch all-b (grid 8192, 6 CTAs/SM, 9.2 waves),
// K2 single launch, K3 single launch with (b,n) reversed so its first
// waves re-read the u tail K1 just left in L2.

#define BB 4
#define II 32
#define NN 32
#define JJ 16
#define HH 32
#define WW 32
#define HW 1024
#define STRIDE_I 524288   // N*J*H*W
#define WT 16             // w tile in K1

// scratch: c_raw [B,I,N,H,W] 16MB, lse [B,I,H,W] 512KB
__device__ float g_craw[BB * II * NN * HW];
__device__ float g_lse[BB * II * HW];

// ---------------------------------------------------------------------------
// K1: per (b, n, h, w-half) slice. 256 threads, 32KB+5KB smem, 6 CTAs/SM.
// Computes v during load (register partials), then c_raw, writes c_raw.
// ---------------------------------------------------------------------------
__global__ void __launch_bounds__(256) k1_craw(const float* __restrict__ u) {
    __shared__ float u_s[II * JJ * WT];            // 32 KB
    __shared__ float4 vpart[256];                  // 4 KB
    __shared__ float v_s[JJ * WT];                 // 1 KB

    const int bid = blockIdx.x;                    // ((b*32+n)*32+h)*2+wh
    const int wh = bid & 1;
    const int h = (bid >> 1) & 31;
    const int n = (bid >> 6) & 31;
    const int b = bid >> 11;
    const int w0 = wh * WT;
    const int tid = threadIdx.x;

    // u element: ((b*II+i)*NN+n)*JJ*HW + j*HW + h*WW + w
    const int base = (b * 1024 + n) * (JJ * HW) + h * WW + w0;

    // load: q = float4 within w-tile (4), j (16), iq = i mod 4 group (4)
    const int q = tid & 3;
    const int j = (tid >> 2) & 15;
    const int iq = tid >> 6;

    float4 vp = make_float4(0.f, 0.f, 0.f, 0.f);
#pragma unroll
    for (int k = 0; k < 8; k++) {
        const int i = 4 * k + iq;
        const float4 val =
            *(const float4*)(u + base + i * STRIDE_I + j * HW + q * 4);
        *(float4*)(&u_s[(i * JJ + j) * WT + q * 4]) = val;
        vp.x += val.x; vp.y += val.y; vp.z += val.z; vp.w += val.w;
    }
    vpart[tid] = vp;
    __syncthreads();

    // combine 4 iq-groups -> v[j][w]
    if (tid < 64) {                                // tid<64 keeps same (j,q)
        const float4 a = vpart[tid];
        const float4 c2 = vpart[tid + 64];
        const float4 c3 = vpart[tid + 128];
        const float4 c4 = vpart[tid + 192];
        float4 r;
        r.x = a.x + c2.x + c3.x + c4.x;
        r.y = a.y + c2.y + c3.y + c4.y;
        r.z = a.z + c2.z + c3.z + c4.z;
        r.w = a.w + c2.w + c3.w + c4.w;
        *(float4*)(&v_s[j * WT + q * 4]) = r;
    }
    __syncthreads();

    // c_raw[i][w] = sum_j u_s[i][j][w] * v[j][w]
    const int wl = tid & 15;
    const int i0 = tid >> 4;                       // 0..15
    float vreg[JJ];
#pragma unroll
    for (int jj = 0; jj < JJ; jj++) vreg[jj] = v_s[jj * WT + wl];

#pragma unroll
    for (int m = 0; m < 2; m++) {
        const int i = i0 + 16 * m;
        float acc = 0.f;
#pragma unroll
        for (int jj = 0; jj < JJ; jj++)
            acc += u_s[(i * JJ + jj) * WT + wl] * vreg[jj];
        g_craw[((b * II + i) * NN + n) * HW + h * WW + w0 + wl] = acc;
    }
}

// ---------------------------------------------------------------------------
// K2: per-pixel (b,i,h,w) log-sum-exp over n of 0.25*c_raw.
// ---------------------------------------------------------------------------
__global__ void __launch_bounds__(256) k2_lse() {
    const int t = blockIdx.x * 256 + threadIdx.x;  // 0..131071
    const int hw = t & 1023;
    const int bi = t >> 10;                        // b*II + i
    const float* p = g_craw + bi * (NN * HW) + hw;

    float vals[NN];
    float m = -3.402823466e+38f;
#pragma unroll
    for (int n = 0; n < NN; n++) {
        vals[n] = 0.25f * p[n * HW];
        m = fmaxf(m, vals[n]);
    }
    float s = 0.f;
#pragma unroll
    for (int n = 0; n < NN; n++) s += expf(vals[n] - m);
    g_lse[t] = m + logf(s);
}

// ---------------------------------------------------------------------------
// K3: per (b, n, h) slice, 512 threads (j,w). (b,n) REVERSED so early CTAs
// hit the u tail K1 left in L2.
// c[i,w] = exp(0.25*c_raw - lse) + bias[i,n]; s[j,w] = sum_i u*c; squash.
// ---------------------------------------------------------------------------
__global__ void __launch_bounds__(512) k3_out(const float* __restrict__ u,
                                             const float* __restrict__ bias,
                                             float* __restrict__ out) {
    __shared__ float c_s[II * WW];                 // 4 KB
    __shared__ float s_s[JJ * WW];                 // 2 KB

    const int bid = blockIdx.x;                    // reversed mapping
    const int h = bid & 31;
    const int n = 31 - ((bid >> 5) & 31);
    const int b = (BB - 1) - (bid >> 10);
    const int tid = threadIdx.x;

#pragma unroll
    for (int t = tid; t < II * WW; t += 512) {
        const int i = t >> 5;
        const int w = t & 31;
        const int hw = h * WW + w;
        const float cr = g_craw[((b * II + i) * NN + n) * HW + hw];
        const float lse = g_lse[(b * II + i) * HW + hw];
        c_s[t] = expf(0.25f * cr - lse) + __ldg(&bias[i * NN + n]);
    }
    __syncthreads();

    const int jj = tid >> 5;                       // 0..15
    const int w = tid & 31;
    const int base = (b * 1024 + n) * (JJ * HW) + h * WW + w + jj * HW;

    float a0 = 0.f, a1 = 0.f, a2 = 0.f, a3 = 0.f;
#pragma unroll
    for (int i = 0; i < II; i += 4) {
        a0 += u[base + (i + 0) * STRIDE_I] * c_s[(i + 0) * 32 + w];
        a1 += u[base + (i + 1) * STRIDE_I] * c_s[(i + 1) * 32 + w];
        a2 += u[base + (i + 2) * STRIDE_I] * c_s[(i + 2) * 32 + w];
        a3 += u[base + (i + 3) * STRIDE_I] * c_s[(i + 3) * 32 + w];
    }
    const float acc = (a0 + a1) + (a2 + a3);

    s_s[tid] = acc;
    __syncthreads();

    float nrm2 = 0.f;
#pragma unroll
    for (int j2 = 0; j2 < JJ; j2++) {
        const float x = s_s[j2 * WW + w];
        nrm2 += x * x;
    }
    const float nrm = sqrtf(nrm2);
    const float factor =
        (1.0f - 1.0f / (expf(nrm) + 1e-20f)) / (nrm + 1e-20f);

    out[((b * NN + n) * JJ + jj) * HW + h * WW + w] = acc * factor;
}

// ---------------------------------------------------------------------------
extern "C" void kernel_launch(void* const* d_in, const int* in_sizes, int n_in,
                              void* d_out, int out_size) {
    const float* u = (const float*)d_in[0];
    const float* bias = (const float*)d_in[1];
    float* out = (float*)d_out;

    k1_craw<<<BB * NN * HH * 2, 256>>>(u);         // 8192 CTAs
    k2_lse<<<(BB * II * HW) / 256, 256>>>();       // 512 CTAs
    k3_out<<<BB * NN * HH, 512>>>(u, bias, out);   // 4096 CTAs
}

// round 5
// speedup vs baseline: 1.3030x; 1.1422x over previous
#include <cuda_runtime.h>
#include <cuda_bf16.h>

// AttentionRouting: u [B=4, I=32, N=32, J=16, H=32, W=32] f32, bias [1,32,32,1,1,1]
//   v = sum_i u; c_raw = sum_j u*v; c = softmax_n(0.25*c_raw) + bias
//   s = sum_i u*c; squash over j.
//
// R5: K1 rewritten as register-resident j-pipeline: per j, one coalesced
// LDG.128 per thread, i-reduction via shfl + tiny smem exchange, c_raw
// accumulated in registers. No u staging in smem. K2/K3 as R4.

#define BB 4
#define II 32
#define NN 32
#define JJ 16
#define HH 32
#define WW 32
#define HW 1024
#define STRIDE_I 524288   // N*J*H*W

// scratch: c_raw [B,I,N,H,W] 16MB, lse [B,I,H,W] 512KB
__device__ float g_craw[BB * II * NN * HW];
__device__ float g_lse[BB * II * HW];

// ---------------------------------------------------------------------------
// K1: CTA = (b,n,h). 256 threads: i = warp*4 + (lane>>3), w-chunk q = lane&7.
// Pipeline over j: LDG.128 -> shfl-reduce i (intra-warp 4) -> vpart smem
// (cross-warp 8) -> shfl -> c_acc += u*v. One barrier per j (double buffer).
// ---------------------------------------------------------------------------
__global__ void __launch_bounds__(256, 6) k1_craw(const float* __restrict__ u) {
    __shared__ float4 vpart[2][8][8];              // [buf][warp][q] = 2 KB

    const int bid = blockIdx.x;                    // (b*NN + n)*HH + h
    const int h = bid & 31;
    const int n = (bid >> 5) & 31;
    const int b = bid >> 10;
    const int tid = threadIdx.x;
    const int lane = tid & 31;
    const int warp = tid >> 5;
    const int q = lane & 7;                        // w float4-chunk
    const int iA = lane >> 3;                      // 0..3
    const int i = warp * 4 + iA;                   // 0..31

    // u[((b*II+i)*NN+n)*JJ*HW + j*HW + h*WW + q*4]
    const float* up = u + ((size_t)((b * II + i) * NN + n)) * (JJ * HW)
                        + h * WW + q * 4;

    float4 cacc = make_float4(0.f, 0.f, 0.f, 0.f);
    float4 cur = *(const float4*)up;

#pragma unroll
    for (int j = 0; j < JJ; j++) {
        float4 nxt = make_float4(0.f, 0.f, 0.f, 0.f);
        if (j + 1 < JJ) nxt = *(const float4*)(up + (j + 1) * HW);

        // stage 1: reduce over iA (4 i's within warp)
        float4 vp = cur;
        vp.x += __shfl_xor_sync(0xffffffffu, vp.x, 8);
        vp.y += __shfl_xor_sync(0xffffffffu, vp.y, 8);
        vp.z += __shfl_xor_sync(0xffffffffu, vp.z, 8);
        vp.w += __shfl_xor_sync(0xffffffffu, vp.w, 8);
        vp.x += __shfl_xor_sync(0xffffffffu, vp.x, 16);
        vp.y += __shfl_xor_sync(0xffffffffu, vp.y, 16);
        vp.z += __shfl_xor_sync(0xffffffffu, vp.z, 16);
        vp.w += __shfl_xor_sync(0xffffffffu, vp.w, 16);
        if (iA == 0) vpart[j & 1][warp][q] = vp;
        __syncthreads();

        // stage 2: reduce over 8 warps; every thread ends with v[j][q-chunk]
        float4 a = vpart[j & 1][iA][q];
        float4 b2 = vpart[j & 1][iA + 4][q];
        float4 t;
        t.x = a.x + b2.x; t.y = a.y + b2.y;
        t.z = a.z + b2.z; t.w = a.w + b2.w;
        t.x += __shfl_xor_sync(0xffffffffu, t.x, 8);
        t.y += __shfl_xor_sync(0xffffffffu, t.y, 8);
        t.z += __shfl_xor_sync(0xffffffffu, t.z, 8);
        t.w += __shfl_xor_sync(0xffffffffu, t.w, 8);
        t.x += __shfl_xor_sync(0xffffffffu, t.x, 16);
        t.y += __shfl_xor_sync(0xffffffffu, t.y, 16);
        t.z += __shfl_xor_sync(0xffffffffu, t.z, 16);
        t.w += __shfl_xor_sync(0xffffffffu, t.w, 16);

        cacc.x += cur.x * t.x;
        cacc.y += cur.y * t.y;
        cacc.z += cur.z * t.z;
        cacc.w += cur.w * t.w;
        cur = nxt;
    }

    *(float4*)(g_craw + ((size_t)((b * II + i) * NN + n)) * HW
               + h * WW + q * 4) = cacc;
}

// ---------------------------------------------------------------------------
// K2: per-pixel (b,i,h,w) log-sum-exp over n of 0.25*c_raw.
// ---------------------------------------------------------------------------
__global__ void __launch_bounds__(256) k2_lse() {
    const int t = blockIdx.x * 256 + threadIdx.x;  // 0..131071
    const int hw = t & 1023;
    const int bi = t >> 10;                        // b*II + i
    const float* p = g_craw + bi * (NN * HW) + hw;

    float vals[NN];
    float m = -3.402823466e+38f;
#pragma unroll
    for (int n = 0; n < NN; n++) {
        vals[n] = 0.25f * p[n * HW];
        m = fmaxf(m, vals[n]);
    }
    float s = 0.f;
#pragma unroll
    for (int n = 0; n < NN; n++) s += expf(vals[n] - m);
    g_lse[t] = m + logf(s);
}

// ---------------------------------------------------------------------------
// K3: per (b, n, h) slice, 512 threads (j,w). (b,n) REVERSED so early CTAs
// hit the u tail K1 left in L2.
// ---------------------------------------------------------------------------
__global__ void __launch_bounds__(512) k3_out(const float* __restrict__ u,
                                             const float* __restrict__ bias,
                                             float* __restrict__ out) {
    __shared__ float c_s[II * WW];                 // 4 KB
    __shared__ float s_s[JJ * WW];                 // 2 KB

    const int bid = blockIdx.x;                    // reversed mapping
    const int h = bid & 31;
    const int n = 31 - ((bid >> 5) & 31);
    const int b = (BB - 1) - (bid >> 10);
    const int tid = threadIdx.x;

#pragma unroll
    for (int t = tid; t < II * WW; t += 512) {
        const int i = t >> 5;
        const int w = t & 31;
        const int hw = h * WW + w;
        const float cr = g_craw[((b * II + i) * NN + n) * HW + hw];
        const float lse = g_lse[(b * II + i) * HW + hw];
        c_s[t] = expf(0.25f * cr - lse) + __ldg(&bias[i * NN + n]);
    }
    __syncthreads();

    const int jj = tid >> 5;                       // 0..15
    const int w = tid & 31;
    const int base = (b * 1024 + n) * (JJ * HW) + h * WW + w + jj * HW;

    float a0 = 0.f, a1 = 0.f, a2 = 0.f, a3 = 0.f;
#pragma unroll
    for (int i = 0; i < II; i += 4) {
        a0 += u[base + (i + 0) * STRIDE_I] * c_s[(i + 0) * 32 + w];
        a1 += u[base + (i + 1) * STRIDE_I] * c_s[(i + 1) * 32 + w];
        a2 += u[base + (i + 2) * STRIDE_I] * c_s[(i + 2) * 32 + w];
        a3 += u[base + (i + 3) * STRIDE_I] * c_s[(i + 3) * 32 + w];
    }
    const float acc = (a0 + a1) + (a2 + a3);

    s_s[tid] = acc;
    __syncthreads();

    float nrm2 = 0.f;
#pragma unroll
    for (int j2 = 0; j2 < JJ; j2++) {
        const float x = s_s[j2 * WW + w];
        nrm2 += x * x;
    }
    const float nrm = sqrtf(nrm2);
    const float factor =
        (1.0f - 1.0f / (expf(nrm) + 1e-20f)) / (nrm + 1e-20f);

    out[((b * NN + n) * JJ + jj) * HW + h * WW + w] = acc * factor;
}

// ---------------------------------------------------------------------------
extern "C" void kernel_launch(void* const* d_in, const int* in_sizes, int n_in,
                              void* d_out, int out_size) {
    const float* u = (const float*)d_in[0];
    const float* bias = (const float*)d_in[1];
    float* out = (float*)d_out;

    k1_craw<<<BB * NN * HH, 256>>>(u);             // 4096 CTAs
    k2_lse<<<(BB * II * HW) / 256, 256>>>();       // 512 CTAs
    k3_out<<<BB * NN * HH, 512>>>(u, bias, out);   // 4096 CTAs
}